// round 12
// baseline (speedup 1.0000x reference)
#include <cuda_runtime.h>
#include <cuda_fp16.h>
#include <cstdint>

#define HDIM   1024
#define SEQ    2048
#define BATCH  2
#define NHEADS 16
#define HEADD  64

// Scratch (__device__ globals; no allocations allowed)
__device__ __half g_qh [BATCH*NHEADS*SEQ*HEADD];   // fp16 Q (post-rope)
__device__ __half g_kh [BATCH*NHEADS*SEQ*HEADD];   // fp16 K (post-rope)
__device__ __half g_vh [BATCH*NHEADS*SEQ*HEADD];   // fp16 V
__device__ __half g_aoh[BATCH*SEQ*HDIM];           // fp16 attention output
__device__ __half g_xh [BATCH*SEQ*HDIM];           // fp16 x
__device__ __half g_wh [4][HDIM*HDIM];             // fp16 Wq,Wk,Wv,Wo

// ---------------------------------------------------------------- helpers
__device__ __forceinline__ float ex2f(float x) {
    float r; asm("ex2.approx.f32 %0,%1;" : "=f"(r) : "f"(x)); return r;
}
__device__ __forceinline__ unsigned sptr(const void* p) {
    return (unsigned)__cvta_generic_to_shared(p);
}
__device__ __forceinline__ void ldsm4(unsigned a[4], unsigned addr) {
    asm volatile("ldmatrix.sync.aligned.m8n8.x4.shared.b16 {%0,%1,%2,%3}, [%4];"
        : "=r"(a[0]), "=r"(a[1]), "=r"(a[2]), "=r"(a[3]) : "r"(addr));
}
__device__ __forceinline__ void ldsm4t(unsigned a[4], unsigned addr) {
    asm volatile("ldmatrix.sync.aligned.m8n8.x4.trans.shared.b16 {%0,%1,%2,%3}, [%4];"
        : "=r"(a[0]), "=r"(a[1]), "=r"(a[2]), "=r"(a[3]) : "r"(addr));
}
__device__ __forceinline__ void mma16(float c[4], const unsigned a[4],
                                      unsigned b0, unsigned b1) {
    asm volatile(
        "mma.sync.aligned.m16n8k16.row.col.f32.f16.f16.f32 "
        "{%0,%1,%2,%3}, {%4,%5,%6,%7}, {%8,%9}, {%0,%1,%2,%3};\n"
        : "+f"(c[0]), "+f"(c[1]), "+f"(c[2]), "+f"(c[3])
        : "r"(a[0]), "r"(a[1]), "r"(a[2]), "r"(a[3]), "r"(b0), "r"(b1));
}
__device__ __forceinline__ unsigned pack2(float a, float b) {
    __half2 h = __floats2half2_rn(a, b);
    return *reinterpret_cast<unsigned*>(&h);
}
__device__ __forceinline__ uint4 pack8(float4 a, float4 b) {
    uint4 r;
    r.x = pack2(a.x, a.y); r.y = pack2(a.z, a.w);
    r.z = pack2(b.x, b.y); r.w = pack2(b.z, b.w);
    return r;
}
__device__ __forceinline__ void cpa16(unsigned d, const void* s) {
    asm volatile("cp.async.cg.shared.global [%0], [%1], 16;\n" :: "r"(d), "l"(s));
}
__device__ __forceinline__ void cp_commit() {
    asm volatile("cp.async.commit_group;\n");
}
template<int N> __device__ __forceinline__ void cp_wait() {
    asm volatile("cp.async.wait_group %0;\n" :: "n"(N));
}

// ---------------------------------------------------------------------------
// f32 -> fp16 bulk convert, all tensors in ONE launch (uint4 chunks of 8).
// chunks: [0, 512K) = x ; then 4 x 128K = Wq, Wk, Wv, Wo
// ---------------------------------------------------------------------------
__global__ __launch_bounds__(256) void cvt_all(
    const float* __restrict__ x,  const float* __restrict__ wq,
    const float* __restrict__ wk, const float* __restrict__ wv,
    const float* __restrict__ wo)
{
    int i = blockIdx.x * 256 + threadIdx.x;
    const float* src; __half* dst; int base;
    if (i < 524288) { src = x; dst = g_xh; base = i; }
    else {
        int j = i - 524288;
        int w = j >> 17;  base = j & 131071;
        src = (w == 0) ? wq : (w == 1) ? wk : (w == 2) ? wv : wo;
        dst = g_wh[w];
    }
    float4 a = ((const float4*)src)[2*base];
    float4 b = ((const float4*)src)[2*base + 1];
    ((uint4*)dst)[base] = pack8(a, b);
}

// ---------------------------------------------------------------------------
// fp16 mma.sync GEMM, compile-time specialized. C[m,n] = sum_k A[m,k]*W[n,k].
// Block 128x128, 8 warps, warp tile 32(M)x64(N). K-slab 64 (stride-72 rows,
// conflict-free ldmatrix), 3-stage cp.async pipeline -> only 16 barriers.
// MODE: 1 -> rope epilogue, blockIdx.z picks (Wq->g_qh | Wk->g_kh)
//       3 -> fp16 scatter g_vh
//       0 -> f32 outF row-major (Wo)
// ---------------------------------------------------------------------------
#define GSTR2 72
#define GBUF2 (128*GSTR2*2)             // 18432 B per stage (A or B)
#define GT_SMEM (6*GBUF2)               // 3 stages x (A+B) = 110592 B

template<int MODE>
__global__ __launch_bounds__(256) void gemm_k(
    float* __restrict__ outF,
    const float* __restrict__ rc, const float* __restrict__ rs)
{
    extern __shared__ __align__(16) __half gsm[];
    __half* As = gsm;                    // 3 x 128*GSTR2
    __half* Bs = gsm + 3*128*GSTR2;

    const __half* A = (MODE == 0) ? g_aoh : g_xh;
    const __half* B = (MODE == 0) ? g_wh[3] : (MODE == 3) ? g_wh[2] : g_wh[blockIdx.z];

    const int m0 = blockIdx.y * 128, n0 = blockIdx.x * 128;
    const int t = threadIdx.x, lane = t & 31, wid = t >> 5;
    const int wm = (wid & 3) * 32, wn = (wid >> 2) * 64;

    // staging: thread t owns row t>>1, halves (t&1)*32 .. +32 (4 x 16B)
    const int grow = t >> 1;
    const int gcol = (t & 1) * 32;
    const __half* Ag = A + (size_t)(m0 + grow) * HDIM + gcol;
    const __half* Bg = B + (size_t)(n0 + grow) * HDIM + gcol;
    const unsigned aSt = sptr(&As[grow * GSTR2 + gcol]);
    const unsigned bSt = sptr(&Bs[grow * GSTR2 + gcol]);

    const int s = lane >> 3, r = lane & 7;
    const unsigned aAddr = sptr(&As[(wm + (s & 1) * 8 + r) * GSTR2 + (s >> 1) * 8]);
    const unsigned bAddr = sptr(&Bs[(wn + (s & 1) * 8 + r) * GSTR2 + (s >> 1) * 8]);

    float c[2][8][4];
    #pragma unroll
    for (int i = 0; i < 2; i++)
        #pragma unroll
        for (int j = 0; j < 8; j++)
            #pragma unroll
            for (int q = 0; q < 4; q++) c[i][j][q] = 0.f;

    #define G_LOAD(sl, buf) do { \
        const __half* _as = Ag + (sl) * 64; \
        const __half* _bs = Bg + (sl) * 64; \
        unsigned _o = (buf) * GBUF2; \
        _Pragma("unroll") for (int _j = 0; _j < 4; _j++) { \
            cpa16(aSt + _o + _j * 16, _as + _j * 8); \
            cpa16(bSt + _o + _j * 16, _bs + _j * 8); \
        } \
        cp_commit(); \
    } while (0)

    G_LOAD(0, 0);
    G_LOAD(1, 1);

    const int NIT = HDIM / 64;           // 16 slabs
    for (int it = 0; it < NIT; it++) {
        const int buf = it % 3;
        cp_wait<1>();
        __syncthreads();
        if (it + 2 < NIT) G_LOAD(it + 2, (it + 2) % 3);
        else              cp_commit();            // keep group count aligned

        const unsigned bo = buf * GBUF2;
        #pragma unroll
        for (int kc = 0; kc < 4; kc++) {
            unsigned aa[2][4], bb[4][4];
            #pragma unroll
            for (int mt = 0; mt < 2; mt++)
                ldsm4(aa[mt], aAddr + bo + mt * (16 * GSTR2 * 2) + kc * 32);
            #pragma unroll
            for (int p = 0; p < 4; p++)
                ldsm4(bb[p], bAddr + bo + p * (16 * GSTR2 * 2) + kc * 32);
            #pragma unroll
            for (int mt = 0; mt < 2; mt++)
                #pragma unroll
                for (int nt = 0; nt < 8; nt++)
                    mma16(c[mt][nt], aa[mt],
                          bb[nt >> 1][(nt & 1) ? 1 : 0],
                          bb[nt >> 1][(nt & 1) ? 3 : 2]);
        }
    }
    cp_wait<0>();

    const int grp = lane >> 2, tig = lane & 3;
    if (MODE == 0) {
        #pragma unroll
        for (int mt = 0; mt < 2; mt++)
            #pragma unroll
            for (int nt = 0; nt < 8; nt++) {
                int m = m0 + wm + mt * 16 + grp;
                int n = n0 + wn + nt * 8 + tig * 2;
                *(float2*)(outF + (size_t)m * HDIM + n)       = make_float2(c[mt][nt][0], c[mt][nt][1]);
                *(float2*)(outF + (size_t)(m + 8) * HDIM + n) = make_float2(c[mt][nt][2], c[mt][nt][3]);
            }
    } else if (MODE == 3) {
        const int h = (n0 + wn) >> 6;
        #pragma unroll
        for (int mt = 0; mt < 2; mt++)
            #pragma unroll
            for (int nt = 0; nt < 8; nt++) {
                int m = m0 + wm + mt * 16 + grp;
                int d = nt * 8 + tig * 2;
                int b = m >> 11, sq = m & (SEQ - 1);
                size_t off = (((size_t)(b * NHEADS + h) * SEQ) + sq) * HEADD + d;
                *(unsigned*)(g_vh + off)             = pack2(c[mt][nt][0], c[mt][nt][1]);
                *(unsigned*)(g_vh + off + 8 * HEADD) = pack2(c[mt][nt][2], c[mt][nt][3]);
            }
    } else {
        // RoPE fused: pair (d, d+32) = (c[mt][nt], c[mt][nt+4]), nt < 4.
        __half* dst = blockIdx.z ? g_kh : g_qh;
        const int h = (n0 + wn) >> 6;
        #pragma unroll
        for (int mt = 0; mt < 2; mt++) {
            #pragma unroll
            for (int half = 0; half < 2; half++) {       // rows grp, grp+8
                int m  = m0 + wm + mt * 16 + grp + half * 8;
                int b  = m >> 11, sq = m & (SEQ - 1);
                size_t base = (((size_t)(b * NHEADS + h) * SEQ) + sq) * HEADD;
                const float* rcp = rc + sq * 32;
                const float* rsp = rs + sq * 32;
                const int q0 = half * 2;                 // c idx 0/1 or 2/3
                #pragma unroll
                for (int nt = 0; nt < 4; nt++) {
                    int d0 = nt * 8 + tig * 2;
                    float cc0 = rcp[d0],     ss0 = rsp[d0];
                    float cc1 = rcp[d0 + 1], ss1 = rsp[d0 + 1];
                    float x1a = c[mt][nt][q0],     x2a = c[mt][nt + 4][q0];
                    float x1b = c[mt][nt][q0 + 1], x2b = c[mt][nt + 4][q0 + 1];
                    *(unsigned*)(dst + base + d0) =
                        pack2(x1a * cc0 - x2a * ss0, x1b * cc1 - x2b * ss1);
                    *(unsigned*)(dst + base + d0 + 32) =
                        pack2(x2a * cc0 + x1a * ss0, x2b * cc1 + x1b * ss1);
                }
            }
        }
    }
}

// ---------------------------------------------------------------------------
// Flash attention: fp16 smem via 3-deep cp.async KV pipeline, ldmatrix.trans
// for V, PERSISTENT Q register fragments, deferred l-sum lane reduction.
// Block = (q-tile 128, bh). 256 thr, 8 warps, 2 blocks/SM.
// smem halves (stride 72): Qs[128][72] | Ks[3][64][72] | Vs[3][64][72]
// ---------------------------------------------------------------------------
#define ASTR 72
#define KVH  (64*ASTR)
#define BUFB (KVH*2)
#define ATT_SMEM ((128*ASTR + 6*KVH) * 2)   // 73728 B

__global__ __launch_bounds__(256, 2) void attn_tc()
{
    extern __shared__ __align__(16) __half smh[];
    __half* Qs  = smh;                   // 128*72
    __half* Ks0 = smh + 128*ASTR;        // 3 x 64*72
    __half* Vs0 = Ks0 + 3*KVH;           // 3 x 64*72

    const int bh = blockIdx.y, qt = blockIdx.x;
    const int t = threadIdx.x, lane = t & 31, wid = t >> 5;
    const int s = lane >> 3, r = lane & 7;
    const int grp = lane >> 2, tig = lane & 3;

    const __half* qp    = g_qh + ((size_t)bh * SEQ + qt * 128) * HEADD;
    const __half* kbase = g_kh + (size_t)bh * SEQ * HEADD;
    const __half* vbase = g_vh + (size_t)bh * SEQ * HEADD;

    // ---- prologue: G0 = Q ; G1 = K0/V0 ; G2 = K1/V1
    {
        const unsigned qDst = sptr(Qs) + ((t >> 1) * ASTR + (t & 1) * 32) * 2;
        const __half* qsrc = qp + (t >> 1) * HEADD + (t & 1) * 32;
        #pragma unroll
        for (int j = 0; j < 4; j++) cpa16(qDst + j * 16, qsrc + j * 8);
    }
    cp_commit();                                       // G0
    const unsigned kDst = sptr(Ks0) + ((t >> 2) * ASTR + (t & 3) * 16) * 2;
    const unsigned vDst = sptr(Vs0) + ((t >> 2) * ASTR + (t & 3) * 16) * 2;
    const int srcoff = (t >> 2) * HEADD + (t & 3) * 16;
    cpa16(kDst,      kbase + srcoff);     cpa16(kDst + 16, kbase + srcoff + 8);
    cpa16(vDst,      vbase + srcoff);     cpa16(vDst + 16, vbase + srcoff + 8);
    cp_commit();                                       // G1
    {
        const size_t t1 = (size_t)64 * HEADD;
        cpa16(kDst + BUFB,      kbase + t1 + srcoff);
        cpa16(kDst + BUFB + 16, kbase + t1 + srcoff + 8);
        cpa16(vDst + BUFB,      vbase + t1 + srcoff);
        cpa16(vDst + BUFB + 16, vbase + t1 + srcoff + 8);
        cp_commit();                                   // G2
    }

    const unsigned qA = sptr(Qs)  + ((wid * 16 + (s & 1) * 8 + r) * ASTR + (s >> 1) * 8) * 2;
    const unsigned kA = sptr(Ks0) + (((s & 1) * 8 + r) * ASTR + (s >> 1) * 8) * 2;
    const unsigned vA = sptr(Vs0) + (((s & 1) * 8 + r) * ASTR + (s >> 1) * 8) * 2;

    // ---- Q fragments: load ONCE into registers
    cp_wait<2>();                                      // G0 (Q) complete
    __syncthreads();
    unsigned qf[4][4];
    #pragma unroll
    for (int kc = 0; kc < 4; kc++) ldsm4(qf[kc], qA + kc * 32);

    const float SC = 0.125f * 1.4426950408889634f;

    float o[8][4];
    #pragma unroll
    for (int nt = 0; nt < 8; nt++)
        { o[nt][0] = o[nt][1] = o[nt][2] = o[nt][3] = 0.f; }
    float m_u = -1e30f, m_d = -1e30f, l_u = 0.f, l_d = 0.f;   // l: per-lane partial

    const int NT = SEQ / 64;
    for (int kt = 0; kt < NT; kt++) {
        const int buf = kt % 3;
        cp_wait<1>();                    // completes G_{kt+1} = tile kt
        __syncthreads();

        // issue tile kt+2 into buffer (kt+2)%3 (clamped; never a live buffer)
        {
            const int kn = (kt + 2 < NT) ? kt + 2 : NT - 1;
            const size_t toff = (size_t)kn * 64 * HEADD;
            const unsigned nb = ((kt + 2) % 3) * BUFB;
            cpa16(kDst + nb,      kbase + toff + srcoff);
            cpa16(kDst + nb + 16, kbase + toff + srcoff + 8);
            cpa16(vDst + nb,      vbase + toff + srcoff);
            cpa16(vDst + nb + 16, vbase + toff + srcoff + 8);
            cp_commit();
        }

        // ---- S = Q K^T (warp: 16 x 64)
        float sc[8][4];
        #pragma unroll
        for (int nt = 0; nt < 8; nt++)
            { sc[nt][0] = sc[nt][1] = sc[nt][2] = sc[nt][3] = 0.f; }
        #pragma unroll
        for (int kc = 0; kc < 4; kc++) {
            unsigned kb[4][4];
            #pragma unroll
            for (int p = 0; p < 4; p++)
                ldsm4(kb[p], kA + buf * BUFB + p * (16 * ASTR * 2) + kc * 32);
            #pragma unroll
            for (int nt = 0; nt < 8; nt++)
                mma16(sc[nt], qf[kc],
                      kb[nt >> 1][(nt & 1) ? 1 : 0],
                      kb[nt >> 1][(nt & 1) ? 3 : 2]);
        }

        // ---- online softmax (max reduced across 4 lanes; l stays per-lane)
        float mu = -1e30f, md = -1e30f;
        #pragma unroll
        for (int nt = 0; nt < 8; nt++) {
            mu = fmaxf(mu, fmaxf(sc[nt][0], sc[nt][1]));
            md = fmaxf(md, fmaxf(sc[nt][2], sc[nt][3]));
        }
        mu = fmaxf(mu, __shfl_xor_sync(0xffffffffu, mu, 1));
        mu = fmaxf(mu, __shfl_xor_sync(0xffffffffu, mu, 2));
        md = fmaxf(md, __shfl_xor_sync(0xffffffffu, md, 1));
        md = fmaxf(md, __shfl_xor_sync(0xffffffffu, md, 2));
        float mnu = fmaxf(m_u, mu), mnd = fmaxf(m_d, md);
        float au = ex2f((m_u - mnu) * SC), ad = ex2f((m_d - mnd) * SC);
        m_u = mnu; m_d = mnd;
        const float bu = -mnu * SC, bd = -mnd * SC;

        float su = 0.f, sd = 0.f;
        #pragma unroll
        for (int nt = 0; nt < 8; nt++) {
            sc[nt][0] = ex2f(fmaf(sc[nt][0], SC, bu));
            sc[nt][1] = ex2f(fmaf(sc[nt][1], SC, bu));
            sc[nt][2] = ex2f(fmaf(sc[nt][2], SC, bd));
            sc[nt][3] = ex2f(fmaf(sc[nt][3], SC, bd));
            su += sc[nt][0] + sc[nt][1];
            sd += sc[nt][2] + sc[nt][3];
        }
        l_u = l_u * au + su;             // per-lane partial (reduced after loop)
        l_d = l_d * ad + sd;
        #pragma unroll
        for (int nt = 0; nt < 8; nt++) {
            o[nt][0] *= au; o[nt][1] *= au;
            o[nt][2] *= ad; o[nt][3] *= ad;
        }

        // ---- O += P V : A-frags = repacked S; B-frags via ldmatrix.trans
        #pragma unroll
        for (int kc = 0; kc < 4; kc++) {
            unsigned af[4];
            af[0] = pack2(sc[2*kc][0],   sc[2*kc][1]);
            af[1] = pack2(sc[2*kc][2],   sc[2*kc][3]);
            af[2] = pack2(sc[2*kc+1][0], sc[2*kc+1][1]);
            af[3] = pack2(sc[2*kc+1][2], sc[2*kc+1][3]);
            #pragma unroll
            for (int p = 0; p < 4; p++) {
                unsigned vb[4];
                ldsm4t(vb, vA + buf * BUFB + kc * (16 * ASTR * 2) + p * 32);
                mma16(o[2*p],   af, vb[0], vb[1]);
                mma16(o[2*p+1], af, vb[2], vb[3]);
            }
        }
    }
    cp_wait<0>();

    // ---- final l reduction across the 4 lanes of each row group
    l_u += __shfl_xor_sync(0xffffffffu, l_u, 1);
    l_u += __shfl_xor_sync(0xffffffffu, l_u, 2);
    l_d += __shfl_xor_sync(0xffffffffu, l_d, 1);
    l_d += __shfl_xor_sync(0xffffffffu, l_d, 2);

    // ---- epilogue: normalize, write fp16 g_aoh [B,S,H]
    const int b = bh >> 4, h = bh & 15;
    const float iu = 1.f / l_u, id = 1.f / l_d;
    const int srow = qt * 128 + wid * 16 + grp;
    __half* obase = g_aoh + ((size_t)(b * SEQ + srow)) * HDIM + h * HEADD;
    #pragma unroll
    for (int nt = 0; nt < 8; nt++) {
        int d = nt * 8 + tig * 2;
        *(unsigned*)(obase + d)            = pack2(o[nt][0] * iu, o[nt][1] * iu);
        *(unsigned*)(obase + 8 * HDIM + d) = pack2(o[nt][2] * id, o[nt][3] * id);
    }
}

// ---------------------------------------------------------------------------
extern "C" void kernel_launch(void* const* d_in, const int* in_sizes, int n_in,
                              void* d_out, int out_size)
{
    const float* x  = (const float*)d_in[0];
    const float* Wq = (const float*)d_in[1];
    const float* Wk = (const float*)d_in[2];
    const float* Wv = (const float*)d_in[3];
    const float* Wo = (const float*)d_in[4];
    const float* rc = (const float*)d_in[5];
    const float* rs = (const float*)d_in[6];
    float* out = (float*)d_out;

    cudaFuncSetAttribute(attn_tc,
                         cudaFuncAttributeMaxDynamicSharedMemorySize, ATT_SMEM);
    cudaFuncSetAttribute(gemm_k<0>,
                         cudaFuncAttributeMaxDynamicSharedMemorySize, GT_SMEM);
    cudaFuncSetAttribute(gemm_k<1>,
                         cudaFuncAttributeMaxDynamicSharedMemorySize, GT_SMEM);
    cudaFuncSetAttribute(gemm_k<3>,
                         cudaFuncAttributeMaxDynamicSharedMemorySize, GT_SMEM);

    cvt_all<<<4096, 256>>>(x, Wq, Wk, Wv, Wo);

    dim3 gQK(HDIM / 128, (BATCH * SEQ) / 128, 2);   // (8, 32, 2) = 512 CTAs
    dim3 g1 (HDIM / 128, (BATCH * SEQ) / 128, 1);   // (8, 32)    = 256 CTAs
    gemm_k<1><<<gQK, 256, GT_SMEM>>>(nullptr, rc, rs);            // Q+K (+rope)
    gemm_k<3><<<g1,  256, GT_SMEM>>>(nullptr, nullptr, nullptr);  // V -> g_vh

    attn_tc<<<dim3(SEQ / 128, BATCH * NHEADS), 256, ATT_SMEM>>>();

    gemm_k<0><<<g1,  256, GT_SMEM>>>(out, nullptr, nullptr);      // Wo -> out
}

// round 13
// speedup vs baseline: 1.0787x; 1.0787x over previous
#include <cuda_runtime.h>
#include <cuda_fp16.h>
#include <cstdint>

#define HDIM   1024
#define SEQ    2048
#define BATCH  2
#define NHEADS 16
#define HEADD  64

// Scratch (__device__ globals; no allocations allowed)
__device__ __half g_qh [BATCH*NHEADS*SEQ*HEADD];   // fp16 Q (post-rope)
__device__ __half g_kh [BATCH*NHEADS*SEQ*HEADD];   // fp16 K (post-rope)
__device__ __half g_vh [BATCH*NHEADS*SEQ*HEADD];   // fp16 V
__device__ __half g_aoh[BATCH*SEQ*HDIM];           // fp16 attention output
__device__ __half g_xh [BATCH*SEQ*HDIM];           // fp16 x
__device__ __half g_wh [4][HDIM*HDIM];             // fp16 Wq,Wk,Wv,Wo

// ---------------------------------------------------------------- helpers
__device__ __forceinline__ float ex2f(float x) {
    float r; asm("ex2.approx.f32 %0,%1;" : "=f"(r) : "f"(x)); return r;
}
__device__ __forceinline__ unsigned sptr(const void* p) {
    return (unsigned)__cvta_generic_to_shared(p);
}
__device__ __forceinline__ void ldsm4(unsigned a[4], unsigned addr) {
    asm volatile("ldmatrix.sync.aligned.m8n8.x4.shared.b16 {%0,%1,%2,%3}, [%4];"
        : "=r"(a[0]), "=r"(a[1]), "=r"(a[2]), "=r"(a[3]) : "r"(addr));
}
__device__ __forceinline__ void ldsm4t(unsigned a[4], unsigned addr) {
    asm volatile("ldmatrix.sync.aligned.m8n8.x4.trans.shared.b16 {%0,%1,%2,%3}, [%4];"
        : "=r"(a[0]), "=r"(a[1]), "=r"(a[2]), "=r"(a[3]) : "r"(addr));
}
__device__ __forceinline__ void mma16(float c[4], const unsigned a[4],
                                      unsigned b0, unsigned b1) {
    asm volatile(
        "mma.sync.aligned.m16n8k16.row.col.f32.f16.f16.f32 "
        "{%0,%1,%2,%3}, {%4,%5,%6,%7}, {%8,%9}, {%0,%1,%2,%3};\n"
        : "+f"(c[0]), "+f"(c[1]), "+f"(c[2]), "+f"(c[3])
        : "r"(a[0]), "r"(a[1]), "r"(a[2]), "r"(a[3]), "r"(b0), "r"(b1));
}
__device__ __forceinline__ unsigned pack2(float a, float b) {
    __half2 h = __floats2half2_rn(a, b);
    return *reinterpret_cast<unsigned*>(&h);
}
__device__ __forceinline__ uint4 pack8(float4 a, float4 b) {
    uint4 r;
    r.x = pack2(a.x, a.y); r.y = pack2(a.z, a.w);
    r.z = pack2(b.x, b.y); r.w = pack2(b.z, b.w);
    return r;
}
__device__ __forceinline__ void cpa16(unsigned d, const void* s) {
    asm volatile("cp.async.cg.shared.global [%0], [%1], 16;\n" :: "r"(d), "l"(s));
}
__device__ __forceinline__ void cp_commit() {
    asm volatile("cp.async.commit_group;\n");
}
template<int N> __device__ __forceinline__ void cp_wait() {
    asm volatile("cp.async.wait_group %0;\n" :: "n"(N));
}

// ---------------------------------------------------------------------------
// f32 -> fp16 bulk convert, all tensors in ONE launch (uint4 chunks of 8).
// chunks: [0, 512K) = x ; then 4 x 128K = Wq, Wk, Wv, Wo
// ---------------------------------------------------------------------------
__global__ __launch_bounds__(256) void cvt_all(
    const float* __restrict__ x,  const float* __restrict__ wq,
    const float* __restrict__ wk, const float* __restrict__ wv,
    const float* __restrict__ wo)
{
    int i = blockIdx.x * 256 + threadIdx.x;
    const float* src; __half* dst; int base;
    if (i < 524288) { src = x; dst = g_xh; base = i; }
    else {
        int j = i - 524288;
        int w = j >> 17;  base = j & 131071;
        src = (w == 0) ? wq : (w == 1) ? wk : (w == 2) ? wv : wo;
        dst = g_wh[w];
    }
    float4 a = ((const float4*)src)[2*base];
    float4 b = ((const float4*)src)[2*base + 1];
    ((uint4*)dst)[base] = pack8(a, b);
}

// ---------------------------------------------------------------------------
// fp16 mma.sync GEMM (R11-proven shape): block 128x128, 8 warps, warp tile
// 32(M)x64(N), K-step 32, 4-stage cp.async pipeline + wait_group<2>.
// MODE 1: QKV projections in ONE launch — blockIdx.z: 0=Wq->rope->g_qh,
//         1=Wk->rope->g_kh, 2=Wv->g_vh.
// MODE 0: Wo GEMM, f32 outF row-major.
// ---------------------------------------------------------------------------
#define GSTR 40
#define GBUFO (128*GSTR*2)              // bytes per A (or B) stage buffer
#define GT_SMEM (8*GBUFO)               // 4 stages x (A+B) = 81920 B

template<int MODE>
__global__ __launch_bounds__(256) void gemm_k(
    float* __restrict__ outF,
    const float* __restrict__ rc, const float* __restrict__ rs)
{
    extern __shared__ __align__(16) __half gsm[];
    __half* As = gsm;                    // 4 x 128*GSTR
    __half* Bs = gsm + 4*128*GSTR;

    const __half* A = (MODE == 0) ? g_aoh : g_xh;
    const __half* B = (MODE == 0) ? g_wh[3] : g_wh[blockIdx.z];

    const int m0 = blockIdx.y * 128, n0 = blockIdx.x * 128;
    const int t = threadIdx.x, lane = t & 31, wid = t >> 5;
    const int wm = (wid & 3) * 32, wn = (wid >> 2) * 64;

    const int grow = t >> 1;
    const int gcol = (t & 1) * 16;
    const __half* Ag = A + (size_t)(m0 + grow) * HDIM + gcol;
    const __half* Bg = B + (size_t)(n0 + grow) * HDIM + gcol;
    const unsigned aSt = sptr(&As[grow * GSTR + gcol]);
    const unsigned bSt = sptr(&Bs[grow * GSTR + gcol]);

    const int s = lane >> 3, r = lane & 7;
    const unsigned aAddr = sptr(&As[(wm + (s & 1) * 8 + r) * GSTR + (s >> 1) * 8]);
    const unsigned bAddr = sptr(&Bs[(wn + (s & 1) * 8 + r) * GSTR + (s >> 1) * 8]);

    float c[2][8][4];
    #pragma unroll
    for (int i = 0; i < 2; i++)
        #pragma unroll
        for (int j = 0; j < 8; j++)
            #pragma unroll
            for (int q = 0; q < 4; q++) c[i][j][q] = 0.f;

    #define G_LOAD(sl, buf) do { \
        const __half* _as = Ag + (sl) * 32; \
        const __half* _bs = Bg + (sl) * 32; \
        unsigned _o = (buf) * GBUFO; \
        cpa16(aSt + _o,      _as);    cpa16(aSt + _o + 16, _as + 8); \
        cpa16(bSt + _o,      _bs);    cpa16(bSt + _o + 16, _bs + 8); \
        cp_commit(); \
    } while (0)

    G_LOAD(0, 0);
    G_LOAD(1, 1);
    G_LOAD(2, 2);

    const int NIT = HDIM / 32;
    for (int it = 0; it < NIT; it++) {
        const int buf = it & 3;
        cp_wait<2>();
        __syncthreads();
        if (it + 3 < NIT) G_LOAD(it + 3, (it + 3) & 3);
        else              cp_commit();            // keep group count aligned

        const unsigned bo = buf * GBUFO;
        #pragma unroll
        for (int kc = 0; kc < 2; kc++) {
            unsigned aa[2][4], bb[4][4];
            #pragma unroll
            for (int mt = 0; mt < 2; mt++)
                ldsm4(aa[mt], aAddr + bo + mt * (16 * GSTR * 2) + kc * 32);
            #pragma unroll
            for (int p = 0; p < 4; p++)
                ldsm4(bb[p], bAddr + bo + p * (16 * GSTR * 2) + kc * 32);
            #pragma unroll
            for (int mt = 0; mt < 2; mt++)
                #pragma unroll
                for (int nt = 0; nt < 8; nt++)
                    mma16(c[mt][nt], aa[mt],
                          bb[nt >> 1][(nt & 1) ? 1 : 0],
                          bb[nt >> 1][(nt & 1) ? 3 : 2]);
        }
    }
    cp_wait<0>();

    const int grp = lane >> 2, tig = lane & 3;
    if (MODE == 0) {
        #pragma unroll
        for (int mt = 0; mt < 2; mt++)
            #pragma unroll
            for (int nt = 0; nt < 8; nt++) {
                int m = m0 + wm + mt * 16 + grp;
                int n = n0 + wn + nt * 8 + tig * 2;
                *(float2*)(outF + (size_t)m * HDIM + n)       = make_float2(c[mt][nt][0], c[mt][nt][1]);
                *(float2*)(outF + (size_t)(m + 8) * HDIM + n) = make_float2(c[mt][nt][2], c[mt][nt][3]);
            }
    } else if (blockIdx.z == 2) {
        // V: plain fp16 scatter into [b,h,s,d]
        const int h = (n0 + wn) >> 6;
        #pragma unroll
        for (int mt = 0; mt < 2; mt++)
            #pragma unroll
            for (int nt = 0; nt < 8; nt++) {
                int m = m0 + wm + mt * 16 + grp;
                int d = nt * 8 + tig * 2;
                int b = m >> 11, sq = m & (SEQ - 1);
                size_t off = (((size_t)(b * NHEADS + h) * SEQ) + sq) * HEADD + d;
                *(unsigned*)(g_vh + off)             = pack2(c[mt][nt][0], c[mt][nt][1]);
                *(unsigned*)(g_vh + off + 8 * HEADD) = pack2(c[mt][nt][2], c[mt][nt][3]);
            }
    } else {
        // Q/K: RoPE fused — pair (d, d+32) = (c[mt][nt], c[mt][nt+4]), nt < 4.
        __half* dst = blockIdx.z ? g_kh : g_qh;
        const int h = (n0 + wn) >> 6;
        #pragma unroll
        for (int mt = 0; mt < 2; mt++) {
            #pragma unroll
            for (int half = 0; half < 2; half++) {       // rows grp, grp+8
                int m  = m0 + wm + mt * 16 + grp + half * 8;
                int b  = m >> 11, sq = m & (SEQ - 1);
                size_t base = (((size_t)(b * NHEADS + h) * SEQ) + sq) * HEADD;
                const float* rcp = rc + sq * 32;
                const float* rsp = rs + sq * 32;
                const int q0 = half * 2;                 // c idx 0/1 or 2/3
                #pragma unroll
                for (int nt = 0; nt < 4; nt++) {
                    int d0 = nt * 8 + tig * 2;
                    float cc0 = rcp[d0],     ss0 = rsp[d0];
                    float cc1 = rcp[d0 + 1], ss1 = rsp[d0 + 1];
                    float x1a = c[mt][nt][q0],     x2a = c[mt][nt + 4][q0];
                    float x1b = c[mt][nt][q0 + 1], x2b = c[mt][nt + 4][q0 + 1];
                    *(unsigned*)(dst + base + d0) =
                        pack2(x1a * cc0 - x2a * ss0, x1b * cc1 - x2b * ss1);
                    *(unsigned*)(dst + base + d0 + 32) =
                        pack2(x2a * cc0 + x1a * ss0, x2b * cc1 + x1b * ss1);
                }
            }
        }
    }
}

// ---------------------------------------------------------------------------
// Flash attention (R12 version): 3-deep cp.async KV pipeline, ldmatrix.trans
// for V, persistent Q register fragments, deferred l-sum lane reduction.
// Block = (q-tile 128, bh). 256 thr, 8 warps, 2 blocks/SM.
// smem halves (stride 72): Qs[128][72] | Ks[3][64][72] | Vs[3][64][72]
// ---------------------------------------------------------------------------
#define ASTR 72
#define KVH  (64*ASTR)
#define BUFB (KVH*2)
#define ATT_SMEM ((128*ASTR + 6*KVH) * 2)   // 73728 B

__global__ __launch_bounds__(256, 2) void attn_tc()
{
    extern __shared__ __align__(16) __half smh[];
    __half* Qs  = smh;                   // 128*72
    __half* Ks0 = smh + 128*ASTR;        // 3 x 64*72
    __half* Vs0 = Ks0 + 3*KVH;           // 3 x 64*72

    const int bh = blockIdx.y, qt = blockIdx.x;
    const int t = threadIdx.x, lane = t & 31, wid = t >> 5;
    const int s = lane >> 3, r = lane & 7;
    const int grp = lane >> 2, tig = lane & 3;

    const __half* qp    = g_qh + ((size_t)bh * SEQ + qt * 128) * HEADD;
    const __half* kbase = g_kh + (size_t)bh * SEQ * HEADD;
    const __half* vbase = g_vh + (size_t)bh * SEQ * HEADD;

    // ---- prologue: G0 = Q ; G1 = K0/V0 ; G2 = K1/V1
    {
        const unsigned qDst = sptr(Qs) + ((t >> 1) * ASTR + (t & 1) * 32) * 2;
        const __half* qsrc = qp + (t >> 1) * HEADD + (t & 1) * 32;
        #pragma unroll
        for (int j = 0; j < 4; j++) cpa16(qDst + j * 16, qsrc + j * 8);
    }
    cp_commit();                                       // G0
    const unsigned kDst = sptr(Ks0) + ((t >> 2) * ASTR + (t & 3) * 16) * 2;
    const unsigned vDst = sptr(Vs0) + ((t >> 2) * ASTR + (t & 3) * 16) * 2;
    const int srcoff = (t >> 2) * HEADD + (t & 3) * 16;
    cpa16(kDst,      kbase + srcoff);     cpa16(kDst + 16, kbase + srcoff + 8);
    cpa16(vDst,      vbase + srcoff);     cpa16(vDst + 16, vbase + srcoff + 8);
    cp_commit();                                       // G1
    {
        const size_t t1 = (size_t)64 * HEADD;
        cpa16(kDst + BUFB,      kbase + t1 + srcoff);
        cpa16(kDst + BUFB + 16, kbase + t1 + srcoff + 8);
        cpa16(vDst + BUFB,      vbase + t1 + srcoff);
        cpa16(vDst + BUFB + 16, vbase + t1 + srcoff + 8);
        cp_commit();                                   // G2
    }

    const unsigned qA = sptr(Qs)  + ((wid * 16 + (s & 1) * 8 + r) * ASTR + (s >> 1) * 8) * 2;
    const unsigned kA = sptr(Ks0) + (((s & 1) * 8 + r) * ASTR + (s >> 1) * 8) * 2;
    const unsigned vA = sptr(Vs0) + (((s & 1) * 8 + r) * ASTR + (s >> 1) * 8) * 2;

    // ---- Q fragments: load ONCE into registers
    cp_wait<2>();                                      // G0 (Q) complete
    __syncthreads();
    unsigned qf[4][4];
    #pragma unroll
    for (int kc = 0; kc < 4; kc++) ldsm4(qf[kc], qA + kc * 32);

    const float SC = 0.125f * 1.4426950408889634f;

    float o[8][4];
    #pragma unroll
    for (int nt = 0; nt < 8; nt++)
        { o[nt][0] = o[nt][1] = o[nt][2] = o[nt][3] = 0.f; }
    float m_u = -1e30f, m_d = -1e30f, l_u = 0.f, l_d = 0.f;   // l: per-lane partial

    const int NT = SEQ / 64;
    for (int kt = 0; kt < NT; kt++) {
        const int buf = kt % 3;
        cp_wait<1>();                    // completes G_{kt+1} = tile kt
        __syncthreads();

        // issue tile kt+2 into buffer (kt+2)%3 (clamped; never a live buffer)
        {
            const int kn = (kt + 2 < NT) ? kt + 2 : NT - 1;
            const size_t toff = (size_t)kn * 64 * HEADD;
            const unsigned nb = ((kt + 2) % 3) * BUFB;
            cpa16(kDst + nb,      kbase + toff + srcoff);
            cpa16(kDst + nb + 16, kbase + toff + srcoff + 8);
            cpa16(vDst + nb,      vbase + toff + srcoff);
            cpa16(vDst + nb + 16, vbase + toff + srcoff + 8);
            cp_commit();
        }

        // ---- S = Q K^T (warp: 16 x 64)
        float sc[8][4];
        #pragma unroll
        for (int nt = 0; nt < 8; nt++)
            { sc[nt][0] = sc[nt][1] = sc[nt][2] = sc[nt][3] = 0.f; }
        #pragma unroll
        for (int kc = 0; kc < 4; kc++) {
            unsigned kb[4][4];
            #pragma unroll
            for (int p = 0; p < 4; p++)
                ldsm4(kb[p], kA + buf * BUFB + p * (16 * ASTR * 2) + kc * 32);
            #pragma unroll
            for (int nt = 0; nt < 8; nt++)
                mma16(sc[nt], qf[kc],
                      kb[nt >> 1][(nt & 1) ? 1 : 0],
                      kb[nt >> 1][(nt & 1) ? 3 : 2]);
        }

        // ---- online softmax (max reduced across 4 lanes; l stays per-lane)
        float mu = -1e30f, md = -1e30f;
        #pragma unroll
        for (int nt = 0; nt < 8; nt++) {
            mu = fmaxf(mu, fmaxf(sc[nt][0], sc[nt][1]));
            md = fmaxf(md, fmaxf(sc[nt][2], sc[nt][3]));
        }
        mu = fmaxf(mu, __shfl_xor_sync(0xffffffffu, mu, 1));
        mu = fmaxf(mu, __shfl_xor_sync(0xffffffffu, mu, 2));
        md = fmaxf(md, __shfl_xor_sync(0xffffffffu, md, 1));
        md = fmaxf(md, __shfl_xor_sync(0xffffffffu, md, 2));
        float mnu = fmaxf(m_u, mu), mnd = fmaxf(m_d, md);
        float au = ex2f((m_u - mnu) * SC), ad = ex2f((m_d - mnd) * SC);
        m_u = mnu; m_d = mnd;
        const float bu = -mnu * SC, bd = -mnd * SC;

        float su = 0.f, sd = 0.f;
        #pragma unroll
        for (int nt = 0; nt < 8; nt++) {
            sc[nt][0] = ex2f(fmaf(sc[nt][0], SC, bu));
            sc[nt][1] = ex2f(fmaf(sc[nt][1], SC, bu));
            sc[nt][2] = ex2f(fmaf(sc[nt][2], SC, bd));
            sc[nt][3] = ex2f(fmaf(sc[nt][3], SC, bd));
            su += sc[nt][0] + sc[nt][1];
            sd += sc[nt][2] + sc[nt][3];
        }
        l_u = l_u * au + su;             // per-lane partial (reduced after loop)
        l_d = l_d * ad + sd;
        #pragma unroll
        for (int nt = 0; nt < 8; nt++) {
            o[nt][0] *= au; o[nt][1] *= au;
            o[nt][2] *= ad; o[nt][3] *= ad;
        }

        // ---- O += P V : A-frags = repacked S; B-frags via ldmatrix.trans
        #pragma unroll
        for (int kc = 0; kc < 4; kc++) {
            unsigned af[4];
            af[0] = pack2(sc[2*kc][0],   sc[2*kc][1]);
            af[1] = pack2(sc[2*kc][2],   sc[2*kc][3]);
            af[2] = pack2(sc[2*kc+1][0], sc[2*kc+1][1]);
            af[3] = pack2(sc[2*kc+1][2], sc[2*kc+1][3]);
            #pragma unroll
            for (int p = 0; p < 4; p++) {
                unsigned vb[4];
                ldsm4t(vb, vA + buf * BUFB + kc * (16 * ASTR * 2) + p * 32);
                mma16(o[2*p],   af, vb[0], vb[1]);
                mma16(o[2*p+1], af, vb[2], vb[3]);
            }
        }
    }
    cp_wait<0>();

    // ---- final l reduction across the 4 lanes of each row group
    l_u += __shfl_xor_sync(0xffffffffu, l_u, 1);
    l_u += __shfl_xor_sync(0xffffffffu, l_u, 2);
    l_d += __shfl_xor_sync(0xffffffffu, l_d, 1);
    l_d += __shfl_xor_sync(0xffffffffu, l_d, 2);

    // ---- epilogue: normalize, write fp16 g_aoh [B,S,H]
    const int b = bh >> 4, h = bh & 15;
    const float iu = 1.f / l_u, id = 1.f / l_d;
    const int srow = qt * 128 + wid * 16 + grp;
    __half* obase = g_aoh + ((size_t)(b * SEQ + srow)) * HDIM + h * HEADD;
    #pragma unroll
    for (int nt = 0; nt < 8; nt++) {
        int d = nt * 8 + tig * 2;
        *(unsigned*)(obase + d)            = pack2(o[nt][0] * iu, o[nt][1] * iu);
        *(unsigned*)(obase + 8 * HDIM + d) = pack2(o[nt][2] * id, o[nt][3] * id);
    }
}

// ---------------------------------------------------------------------------
extern "C" void kernel_launch(void* const* d_in, const int* in_sizes, int n_in,
                              void* d_out, int out_size)
{
    const float* x  = (const float*)d_in[0];
    const float* Wq = (const float*)d_in[1];
    const float* Wk = (const float*)d_in[2];
    const float* Wv = (const float*)d_in[3];
    const float* Wo = (const float*)d_in[4];
    const float* rc = (const float*)d_in[5];
    const float* rs = (const float*)d_in[6];
    float* out = (float*)d_out;

    cudaFuncSetAttribute(attn_tc,
                         cudaFuncAttributeMaxDynamicSharedMemorySize, ATT_SMEM);
    cudaFuncSetAttribute(gemm_k<0>,
                         cudaFuncAttributeMaxDynamicSharedMemorySize, GT_SMEM);
    cudaFuncSetAttribute(gemm_k<1>,
                         cudaFuncAttributeMaxDynamicSharedMemorySize, GT_SMEM);

    cvt_all<<<4096, 256>>>(x, Wq, Wk, Wv, Wo);

    dim3 gQKV(HDIM / 128, (BATCH * SEQ) / 128, 3);  // (8, 32, 3) = 768 CTAs
    dim3 g1  (HDIM / 128, (BATCH * SEQ) / 128, 1);  // (8, 32)    = 256 CTAs
    gemm_k<1><<<gQKV, 256, GT_SMEM>>>(nullptr, rc, rs);      // Q+K (+rope) + V

    attn_tc<<<dim3(SEQ / 128, BATCH * NHEADS), 256, ATT_SMEM>>>();

    gemm_k<0><<<g1,  256, GT_SMEM>>>(out, nullptr, nullptr); // Wo -> out
}

// round 14
// speedup vs baseline: 1.0871x; 1.0078x over previous
#include <cuda_runtime.h>
#include <cuda_fp16.h>
#include <cstdint>

#define HDIM   1024
#define SEQ    2048
#define BATCH  2
#define NHEADS 16
#define HEADD  64

// Scratch (__device__ globals; no allocations allowed)
__device__ __half g_qh [BATCH*NHEADS*SEQ*HEADD];   // fp16 Q (post-rope)
__device__ __half g_kh [BATCH*NHEADS*SEQ*HEADD];   // fp16 K (post-rope)
__device__ __half g_vh [BATCH*NHEADS*SEQ*HEADD];   // fp16 V
__device__ __half g_aoh[BATCH*SEQ*HDIM];           // fp16 attention output
__device__ __half g_xh [BATCH*SEQ*HDIM];           // fp16 x
__device__ __half g_wh [4][HDIM*HDIM];             // fp16 Wq,Wk,Wv,Wo

// ---------------------------------------------------------------- helpers
__device__ __forceinline__ float ex2f(float x) {
    float r; asm("ex2.approx.f32 %0,%1;" : "=f"(r) : "f"(x)); return r;
}
__device__ __forceinline__ unsigned sptr(const void* p) {
    return (unsigned)__cvta_generic_to_shared(p);
}
__device__ __forceinline__ void ldsm4(unsigned a[4], unsigned addr) {
    asm volatile("ldmatrix.sync.aligned.m8n8.x4.shared.b16 {%0,%1,%2,%3}, [%4];"
        : "=r"(a[0]), "=r"(a[1]), "=r"(a[2]), "=r"(a[3]) : "r"(addr));
}
__device__ __forceinline__ void ldsm4t(unsigned a[4], unsigned addr) {
    asm volatile("ldmatrix.sync.aligned.m8n8.x4.trans.shared.b16 {%0,%1,%2,%3}, [%4];"
        : "=r"(a[0]), "=r"(a[1]), "=r"(a[2]), "=r"(a[3]) : "r"(addr));
}
__device__ __forceinline__ void mma16(float c[4], const unsigned a[4],
                                      unsigned b0, unsigned b1) {
    asm volatile(
        "mma.sync.aligned.m16n8k16.row.col.f32.f16.f16.f32 "
        "{%0,%1,%2,%3}, {%4,%5,%6,%7}, {%8,%9}, {%0,%1,%2,%3};\n"
        : "+f"(c[0]), "+f"(c[1]), "+f"(c[2]), "+f"(c[3])
        : "r"(a[0]), "r"(a[1]), "r"(a[2]), "r"(a[3]), "r"(b0), "r"(b1));
}
__device__ __forceinline__ unsigned pack2(float a, float b) {
    __half2 h = __floats2half2_rn(a, b);
    return *reinterpret_cast<unsigned*>(&h);
}
__device__ __forceinline__ uint4 pack8(float4 a, float4 b) {
    uint4 r;
    r.x = pack2(a.x, a.y); r.y = pack2(a.z, a.w);
    r.z = pack2(b.x, b.y); r.w = pack2(b.z, b.w);
    return r;
}
__device__ __forceinline__ void cpa16(unsigned d, const void* s) {
    asm volatile("cp.async.cg.shared.global [%0], [%1], 16;\n" :: "r"(d), "l"(s));
}
__device__ __forceinline__ void cp_commit() {
    asm volatile("cp.async.commit_group;\n");
}
template<int N> __device__ __forceinline__ void cp_wait() {
    asm volatile("cp.async.wait_group %0;\n" :: "n"(N));
}

// ---------------------------------------------------------------------------
// f32 -> fp16 bulk convert, all tensors in ONE launch (uint4 chunks of 8).
// chunks: [0, 512K) = x ; then 4 x 128K = Wq, Wk, Wv, Wo
// ---------------------------------------------------------------------------
__global__ __launch_bounds__(256) void cvt_all(
    const float* __restrict__ x,  const float* __restrict__ wq,
    const float* __restrict__ wk, const float* __restrict__ wv,
    const float* __restrict__ wo)
{
    int i = blockIdx.x * 256 + threadIdx.x;
    const float* src; __half* dst; int base;
    if (i < 524288) { src = x; dst = g_xh; base = i; }
    else {
        int j = i - 524288;
        int w = j >> 17;  base = j & 131071;
        src = (w == 0) ? wq : (w == 1) ? wk : (w == 2) ? wv : wo;
        dst = g_wh[w];
    }
    float4 a = ((const float4*)src)[2*base];
    float4 b = ((const float4*)src)[2*base + 1];
    ((uint4*)dst)[base] = pack8(a, b);
}

// ---------------------------------------------------------------------------
// fp16 mma.sync GEMM: block 128x128, 8 warps, warp tile 32(M)x64(N), K-step
// 32, 4 stage buffers — TWO slabs processed per barrier (race-free: loads
// issued after the sync target buffers last read in the PREVIOUS iteration;
// they have a full 64-mma iteration to land before the next wait<0>).
// MODE 1: QKV in ONE launch — blockIdx.z: 0=Wq->rope->g_qh, 1=Wk->rope->g_kh,
//         2=Wv->g_vh.   MODE 0: Wo GEMM, f32 outF row-major.
// ---------------------------------------------------------------------------
#define GSTR 40
#define GBUFO (128*GSTR*2)              // bytes per A (or B) stage buffer
#define GT_SMEM (8*GBUFO)               // 4 stages x (A+B) = 81920 B

template<int MODE>
__global__ __launch_bounds__(256) void gemm_k(
    float* __restrict__ outF,
    const float* __restrict__ rc, const float* __restrict__ rs)
{
    extern __shared__ __align__(16) __half gsm[];
    __half* As = gsm;                    // 4 x 128*GSTR
    __half* Bs = gsm + 4*128*GSTR;

    const __half* A = (MODE == 0) ? g_aoh : g_xh;
    const __half* B = (MODE == 0) ? g_wh[3] : g_wh[blockIdx.z];

    const int m0 = blockIdx.y * 128, n0 = blockIdx.x * 128;
    const int t = threadIdx.x, lane = t & 31, wid = t >> 5;
    const int wm = (wid & 3) * 32, wn = (wid >> 2) * 64;

    const int grow = t >> 1;
    const int gcol = (t & 1) * 16;
    const __half* Ag = A + (size_t)(m0 + grow) * HDIM + gcol;
    const __half* Bg = B + (size_t)(n0 + grow) * HDIM + gcol;
    const unsigned aSt = sptr(&As[grow * GSTR + gcol]);
    const unsigned bSt = sptr(&Bs[grow * GSTR + gcol]);

    const int s = lane >> 3, r = lane & 7;
    const unsigned aAddr = sptr(&As[(wm + (s & 1) * 8 + r) * GSTR + (s >> 1) * 8]);
    const unsigned bAddr = sptr(&Bs[(wn + (s & 1) * 8 + r) * GSTR + (s >> 1) * 8]);

    float c[2][8][4];
    #pragma unroll
    for (int i = 0; i < 2; i++)
        #pragma unroll
        for (int j = 0; j < 8; j++)
            #pragma unroll
            for (int q = 0; q < 4; q++) c[i][j][q] = 0.f;

    #define G_LOAD(sl, buf) do { \
        const __half* _as = Ag + (sl) * 32; \
        const __half* _bs = Bg + (sl) * 32; \
        unsigned _o = (buf) * GBUFO; \
        cpa16(aSt + _o,      _as);    cpa16(aSt + _o + 16, _as + 8); \
        cpa16(bSt + _o,      _bs);    cpa16(bSt + _o + 16, _bs + 8); \
        cp_commit(); \
    } while (0)

    G_LOAD(0, 0);
    G_LOAD(1, 1);

    const int NSL = HDIM / 32;           // 32 slabs, 2 per iteration
    for (int it = 0; it < NSL; it += 2) {
        cp_wait<0>();                    // slabs it, it+1 complete
        __syncthreads();                 // all warps done with bufs (it+2)&3,(it+3)&3
        if (it + 2 < NSL) {              // prefetch next pair into freed buffers
            G_LOAD(it + 2, (it + 2) & 3);
            G_LOAD(it + 3, (it + 3) & 3);
        }

        #pragma unroll
        for (int h2 = 0; h2 < 2; h2++) { // two slabs back-to-back, one barrier
            const unsigned bo = ((it + h2) & 3) * GBUFO;
            #pragma unroll
            for (int kc = 0; kc < 2; kc++) {
                unsigned aa[2][4], bb[4][4];
                #pragma unroll
                for (int mt = 0; mt < 2; mt++)
                    ldsm4(aa[mt], aAddr + bo + mt * (16 * GSTR * 2) + kc * 32);
                #pragma unroll
                for (int p = 0; p < 4; p++)
                    ldsm4(bb[p], bAddr + bo + p * (16 * GSTR * 2) + kc * 32);
                #pragma unroll
                for (int mt = 0; mt < 2; mt++)
                    #pragma unroll
                    for (int nt = 0; nt < 8; nt++)
                        mma16(c[mt][nt], aa[mt],
                              bb[nt >> 1][(nt & 1) ? 1 : 0],
                              bb[nt >> 1][(nt & 1) ? 3 : 2]);
            }
        }
    }

    const int grp = lane >> 2, tig = lane & 3;
    if (MODE == 0) {
        #pragma unroll
        for (int mt = 0; mt < 2; mt++)
            #pragma unroll
            for (int nt = 0; nt < 8; nt++) {
                int m = m0 + wm + mt * 16 + grp;
                int n = n0 + wn + nt * 8 + tig * 2;
                *(float2*)(outF + (size_t)m * HDIM + n)       = make_float2(c[mt][nt][0], c[mt][nt][1]);
                *(float2*)(outF + (size_t)(m + 8) * HDIM + n) = make_float2(c[mt][nt][2], c[mt][nt][3]);
            }
    } else if (blockIdx.z == 2) {
        // V: plain fp16 scatter into [b,h,s,d]
        const int h = (n0 + wn) >> 6;
        #pragma unroll
        for (int mt = 0; mt < 2; mt++)
            #pragma unroll
            for (int nt = 0; nt < 8; nt++) {
                int m = m0 + wm + mt * 16 + grp;
                int d = nt * 8 + tig * 2;
                int b = m >> 11, sq = m & (SEQ - 1);
                size_t off = (((size_t)(b * NHEADS + h) * SEQ) + sq) * HEADD + d;
                *(unsigned*)(g_vh + off)             = pack2(c[mt][nt][0], c[mt][nt][1]);
                *(unsigned*)(g_vh + off + 8 * HEADD) = pack2(c[mt][nt][2], c[mt][nt][3]);
            }
    } else {
        // Q/K: RoPE fused — pair (d, d+32) = (c[mt][nt], c[mt][nt+4]), nt < 4.
        __half* dst = blockIdx.z ? g_kh : g_qh;
        const int h = (n0 + wn) >> 6;
        #pragma unroll
        for (int mt = 0; mt < 2; mt++) {
            #pragma unroll
            for (int half = 0; half < 2; half++) {       // rows grp, grp+8
                int m  = m0 + wm + mt * 16 + grp + half * 8;
                int b  = m >> 11, sq = m & (SEQ - 1);
                size_t base = (((size_t)(b * NHEADS + h) * SEQ) + sq) * HEADD;
                const float* rcp = rc + sq * 32;
                const float* rsp = rs + sq * 32;
                const int q0 = half * 2;                 // c idx 0/1 or 2/3
                #pragma unroll
                for (int nt = 0; nt < 4; nt++) {
                    int d0 = nt * 8 + tig * 2;
                    float cc0 = rcp[d0],     ss0 = rsp[d0];
                    float cc1 = rcp[d0 + 1], ss1 = rsp[d0 + 1];
                    float x1a = c[mt][nt][q0],     x2a = c[mt][nt + 4][q0];
                    float x1b = c[mt][nt][q0 + 1], x2b = c[mt][nt + 4][q0 + 1];
                    *(unsigned*)(dst + base + d0) =
                        pack2(x1a * cc0 - x2a * ss0, x1b * cc1 - x2b * ss1);
                    *(unsigned*)(dst + base + d0 + 32) =
                        pack2(x2a * cc0 + x1a * ss0, x2b * cc1 + x1b * ss1);
                }
            }
        }
    }
}

// ---------------------------------------------------------------------------
// Flash attention (unchanged from R13): 3-deep cp.async KV pipeline,
// ldmatrix.trans for V, persistent Q fragments, deferred l-sum reduction.
// Block = (q-tile 128, bh). 256 thr, 8 warps, 2 blocks/SM.
// ---------------------------------------------------------------------------
#define ASTR 72
#define KVH  (64*ASTR)
#define BUFB (KVH*2)
#define ATT_SMEM ((128*ASTR + 6*KVH) * 2)   // 73728 B

__global__ __launch_bounds__(256, 2) void attn_tc()
{
    extern __shared__ __align__(16) __half smh[];
    __half* Qs  = smh;                   // 128*72
    __half* Ks0 = smh + 128*ASTR;        // 3 x 64*72
    __half* Vs0 = Ks0 + 3*KVH;           // 3 x 64*72

    const int bh = blockIdx.y, qt = blockIdx.x;
    const int t = threadIdx.x, lane = t & 31, wid = t >> 5;
    const int s = lane >> 3, r = lane & 7;
    const int grp = lane >> 2, tig = lane & 3;

    const __half* qp    = g_qh + ((size_t)bh * SEQ + qt * 128) * HEADD;
    const __half* kbase = g_kh + (size_t)bh * SEQ * HEADD;
    const __half* vbase = g_vh + (size_t)bh * SEQ * HEADD;

    // ---- prologue: G0 = Q ; G1 = K0/V0 ; G2 = K1/V1
    {
        const unsigned qDst = sptr(Qs) + ((t >> 1) * ASTR + (t & 1) * 32) * 2;
        const __half* qsrc = qp + (t >> 1) * HEADD + (t & 1) * 32;
        #pragma unroll
        for (int j = 0; j < 4; j++) cpa16(qDst + j * 16, qsrc + j * 8);
    }
    cp_commit();                                       // G0
    const unsigned kDst = sptr(Ks0) + ((t >> 2) * ASTR + (t & 3) * 16) * 2;
    const unsigned vDst = sptr(Vs0) + ((t >> 2) * ASTR + (t & 3) * 16) * 2;
    const int srcoff = (t >> 2) * HEADD + (t & 3) * 16;
    cpa16(kDst,      kbase + srcoff);     cpa16(kDst + 16, kbase + srcoff + 8);
    cpa16(vDst,      vbase + srcoff);     cpa16(vDst + 16, vbase + srcoff + 8);
    cp_commit();                                       // G1
    {
        const size_t t1 = (size_t)64 * HEADD;
        cpa16(kDst + BUFB,      kbase + t1 + srcoff);
        cpa16(kDst + BUFB + 16, kbase + t1 + srcoff + 8);
        cpa16(vDst + BUFB,      vbase + t1 + srcoff);
        cpa16(vDst + BUFB + 16, vbase + t1 + srcoff + 8);
        cp_commit();                                   // G2
    }

    const unsigned qA = sptr(Qs)  + ((wid * 16 + (s & 1) * 8 + r) * ASTR + (s >> 1) * 8) * 2;
    const unsigned kA = sptr(Ks0) + (((s & 1) * 8 + r) * ASTR + (s >> 1) * 8) * 2;
    const unsigned vA = sptr(Vs0) + (((s & 1) * 8 + r) * ASTR + (s >> 1) * 8) * 2;

    // ---- Q fragments: load ONCE into registers
    cp_wait<2>();                                      // G0 (Q) complete
    __syncthreads();
    unsigned qf[4][4];
    #pragma unroll
    for (int kc = 0; kc < 4; kc++) ldsm4(qf[kc], qA + kc * 32);

    const float SC = 0.125f * 1.4426950408889634f;

    float o[8][4];
    #pragma unroll
    for (int nt = 0; nt < 8; nt++)
        { o[nt][0] = o[nt][1] = o[nt][2] = o[nt][3] = 0.f; }
    float m_u = -1e30f, m_d = -1e30f, l_u = 0.f, l_d = 0.f;   // l: per-lane partial

    const int NT = SEQ / 64;
    for (int kt = 0; kt < NT; kt++) {
        const int buf = kt % 3;
        cp_wait<1>();                    // completes G_{kt+1} = tile kt
        __syncthreads();

        // issue tile kt+2 into buffer (kt+2)%3 (clamped; never a live buffer)
        {
            const int kn = (kt + 2 < NT) ? kt + 2 : NT - 1;
            const size_t toff = (size_t)kn * 64 * HEADD;
            const unsigned nb = ((kt + 2) % 3) * BUFB;
            cpa16(kDst + nb,      kbase + toff + srcoff);
            cpa16(kDst + nb + 16, kbase + toff + srcoff + 8);
            cpa16(vDst + nb,      vbase + toff + srcoff);
            cpa16(vDst + nb + 16, vbase + toff + srcoff + 8);
            cp_commit();
        }

        // ---- S = Q K^T (warp: 16 x 64)
        float sc[8][4];
        #pragma unroll
        for (int nt = 0; nt < 8; nt++)
            { sc[nt][0] = sc[nt][1] = sc[nt][2] = sc[nt][3] = 0.f; }
        #pragma unroll
        for (int kc = 0; kc < 4; kc++) {
            unsigned kb[4][4];
            #pragma unroll
            for (int p = 0; p < 4; p++)
                ldsm4(kb[p], kA + buf * BUFB + p * (16 * ASTR * 2) + kc * 32);
            #pragma unroll
            for (int nt = 0; nt < 8; nt++)
                mma16(sc[nt], qf[kc],
                      kb[nt >> 1][(nt & 1) ? 1 : 0],
                      kb[nt >> 1][(nt & 1) ? 3 : 2]);
        }

        // ---- online softmax (max reduced across 4 lanes; l stays per-lane)
        float mu = -1e30f, md = -1e30f;
        #pragma unroll
        for (int nt = 0; nt < 8; nt++) {
            mu = fmaxf(mu, fmaxf(sc[nt][0], sc[nt][1]));
            md = fmaxf(md, fmaxf(sc[nt][2], sc[nt][3]));
        }
        mu = fmaxf(mu, __shfl_xor_sync(0xffffffffu, mu, 1));
        mu = fmaxf(mu, __shfl_xor_sync(0xffffffffu, mu, 2));
        md = fmaxf(md, __shfl_xor_sync(0xffffffffu, md, 1));
        md = fmaxf(md, __shfl_xor_sync(0xffffffffu, md, 2));
        float mnu = fmaxf(m_u, mu), mnd = fmaxf(m_d, md);
        float au = ex2f((m_u - mnu) * SC), ad = ex2f((m_d - mnd) * SC);
        m_u = mnu; m_d = mnd;
        const float bu = -mnu * SC, bd = -mnd * SC;

        float su = 0.f, sd = 0.f;
        #pragma unroll
        for (int nt = 0; nt < 8; nt++) {
            sc[nt][0] = ex2f(fmaf(sc[nt][0], SC, bu));
            sc[nt][1] = ex2f(fmaf(sc[nt][1], SC, bu));
            sc[nt][2] = ex2f(fmaf(sc[nt][2], SC, bd));
            sc[nt][3] = ex2f(fmaf(sc[nt][3], SC, bd));
            su += sc[nt][0] + sc[nt][1];
            sd += sc[nt][2] + sc[nt][3];
        }
        l_u = l_u * au + su;             // per-lane partial (reduced after loop)
        l_d = l_d * ad + sd;
        #pragma unroll
        for (int nt = 0; nt < 8; nt++) {
            o[nt][0] *= au; o[nt][1] *= au;
            o[nt][2] *= ad; o[nt][3] *= ad;
        }

        // ---- O += P V : A-frags = repacked S; B-frags via ldmatrix.trans
        #pragma unroll
        for (int kc = 0; kc < 4; kc++) {
            unsigned af[4];
            af[0] = pack2(sc[2*kc][0],   sc[2*kc][1]);
            af[1] = pack2(sc[2*kc][2],   sc[2*kc][3]);
            af[2] = pack2(sc[2*kc+1][0], sc[2*kc+1][1]);
            af[3] = pack2(sc[2*kc+1][2], sc[2*kc+1][3]);
            #pragma unroll
            for (int p = 0; p < 4; p++) {
                unsigned vb[4];
                ldsm4t(vb, vA + buf * BUFB + kc * (16 * ASTR * 2) + p * 32);
                mma16(o[2*p],   af, vb[0], vb[1]);
                mma16(o[2*p+1], af, vb[2], vb[3]);
            }
        }
    }
    cp_wait<0>();

    // ---- final l reduction across the 4 lanes of each row group
    l_u += __shfl_xor_sync(0xffffffffu, l_u, 1);
    l_u += __shfl_xor_sync(0xffffffffu, l_u, 2);
    l_d += __shfl_xor_sync(0xffffffffu, l_d, 1);
    l_d += __shfl_xor_sync(0xffffffffu, l_d, 2);

    // ---- epilogue: normalize, write fp16 g_aoh [B,S,H]
    const int b = bh >> 4, h = bh & 15;
    const float iu = 1.f / l_u, id = 1.f / l_d;
    const int srow = qt * 128 + wid * 16 + grp;
    __half* obase = g_aoh + ((size_t)(b * SEQ + srow)) * HDIM + h * HEADD;
    #pragma unroll
    for (int nt = 0; nt < 8; nt++) {
        int d = nt * 8 + tig * 2;
        *(unsigned*)(obase + d)            = pack2(o[nt][0] * iu, o[nt][1] * iu);
        *(unsigned*)(obase + 8 * HDIM + d) = pack2(o[nt][2] * id, o[nt][3] * id);
    }
}

// ---------------------------------------------------------------------------
extern "C" void kernel_launch(void* const* d_in, const int* in_sizes, int n_in,
                              void* d_out, int out_size)
{
    const float* x  = (const float*)d_in[0];
    const float* Wq = (const float*)d_in[1];
    const float* Wk = (const float*)d_in[2];
    const float* Wv = (const float*)d_in[3];
    const float* Wo = (const float*)d_in[4];
    const float* rc = (const float*)d_in[5];
    const float* rs = (const float*)d_in[6];
    float* out = (float*)d_out;

    cudaFuncSetAttribute(attn_tc,
                         cudaFuncAttributeMaxDynamicSharedMemorySize, ATT_SMEM);
    cudaFuncSetAttribute(gemm_k<0>,
                         cudaFuncAttributeMaxDynamicSharedMemorySize, GT_SMEM);
    cudaFuncSetAttribute(gemm_k<1>,
                         cudaFuncAttributeMaxDynamicSharedMemorySize, GT_SMEM);

    cvt_all<<<4096, 256>>>(x, Wq, Wk, Wv, Wo);

    dim3 gQKV(HDIM / 128, (BATCH * SEQ) / 128, 3);  // (8, 32, 3) = 768 CTAs
    dim3 g1  (HDIM / 128, (BATCH * SEQ) / 128, 1);  // (8, 32)    = 256 CTAs
    gemm_k<1><<<gQKV, 256, GT_SMEM>>>(nullptr, rc, rs);      // Q+K (+rope) + V

    attn_tc<<<dim3(SEQ / 128, BATCH * NHEADS), 256, ATT_SMEM>>>();

    gemm_k<0><<<g1,  256, GT_SMEM>>>(out, nullptr, nullptr); // Wo -> out
}

// round 15
// speedup vs baseline: 1.0937x; 1.0062x over previous
#include <cuda_runtime.h>
#include <cuda_fp16.h>
#include <cstdint>

#define HDIM   1024
#define SEQ    2048
#define BATCH  2
#define NHEADS 16
#define HEADD  64

// Scratch (__device__ globals; no allocations allowed)
__device__ __half g_qh [BATCH*NHEADS*SEQ*HEADD];   // fp16 Q (post-rope)
__device__ __half g_kh [BATCH*NHEADS*SEQ*HEADD];   // fp16 K (post-rope)
__device__ __half g_vh [BATCH*NHEADS*SEQ*HEADD];   // fp16 V
__device__ __half g_aoh[BATCH*SEQ*HDIM];           // fp16 attention output
__device__ __half g_xh [BATCH*SEQ*HDIM];           // fp16 x
__device__ __half g_wh [4][HDIM*HDIM];             // fp16 Wq,Wk,Wv,Wo

// ---------------------------------------------------------------- helpers
__device__ __forceinline__ float ex2f(float x) {
    float r; asm("ex2.approx.f32 %0,%1;" : "=f"(r) : "f"(x)); return r;
}
__device__ __forceinline__ unsigned sptr(const void* p) {
    return (unsigned)__cvta_generic_to_shared(p);
}
__device__ __forceinline__ void ldsm4(unsigned a[4], unsigned addr) {
    asm volatile("ldmatrix.sync.aligned.m8n8.x4.shared.b16 {%0,%1,%2,%3}, [%4];"
        : "=r"(a[0]), "=r"(a[1]), "=r"(a[2]), "=r"(a[3]) : "r"(addr));
}
__device__ __forceinline__ void ldsm4t(unsigned a[4], unsigned addr) {
    asm volatile("ldmatrix.sync.aligned.m8n8.x4.trans.shared.b16 {%0,%1,%2,%3}, [%4];"
        : "=r"(a[0]), "=r"(a[1]), "=r"(a[2]), "=r"(a[3]) : "r"(addr));
}
__device__ __forceinline__ void mma16(float c[4], const unsigned a[4],
                                      unsigned b0, unsigned b1) {
    asm volatile(
        "mma.sync.aligned.m16n8k16.row.col.f32.f16.f16.f32 "
        "{%0,%1,%2,%3}, {%4,%5,%6,%7}, {%8,%9}, {%0,%1,%2,%3};\n"
        : "+f"(c[0]), "+f"(c[1]), "+f"(c[2]), "+f"(c[3])
        : "r"(a[0]), "r"(a[1]), "r"(a[2]), "r"(a[3]), "r"(b0), "r"(b1));
}
// D = A*B + 0 (C is a single broadcast zero register; no per-tile zero MOVs)
__device__ __forceinline__ void mma16_z(float d[4], const unsigned a[4],
                                        unsigned b0, unsigned b1) {
    asm volatile(
        "mma.sync.aligned.m16n8k16.row.col.f32.f16.f16.f32 "
        "{%0,%1,%2,%3}, {%4,%5,%6,%7}, {%8,%9}, {%10,%10,%10,%10};\n"
        : "=f"(d[0]), "=f"(d[1]), "=f"(d[2]), "=f"(d[3])
        : "r"(a[0]), "r"(a[1]), "r"(a[2]), "r"(a[3]), "r"(b0), "r"(b1),
          "f"(0.f));
}
__device__ __forceinline__ unsigned pack2(float a, float b) {
    __half2 h = __floats2half2_rn(a, b);
    return *reinterpret_cast<unsigned*>(&h);
}
__device__ __forceinline__ uint4 pack8(float4 a, float4 b) {
    uint4 r;
    r.x = pack2(a.x, a.y); r.y = pack2(a.z, a.w);
    r.z = pack2(b.x, b.y); r.w = pack2(b.z, b.w);
    return r;
}
__device__ __forceinline__ void cpa16(unsigned d, const void* s) {
    asm volatile("cp.async.cg.shared.global [%0], [%1], 16;\n" :: "r"(d), "l"(s));
}
__device__ __forceinline__ void cp_commit() {
    asm volatile("cp.async.commit_group;\n");
}
template<int N> __device__ __forceinline__ void cp_wait() {
    asm volatile("cp.async.wait_group %0;\n" :: "n"(N));
}

// ---------------------------------------------------------------------------
// f32 -> fp16 bulk convert, all tensors in ONE launch (uint4 chunks of 8).
// ---------------------------------------------------------------------------
__global__ __launch_bounds__(256) void cvt_all(
    const float* __restrict__ x,  const float* __restrict__ wq,
    const float* __restrict__ wk, const float* __restrict__ wv,
    const float* __restrict__ wo)
{
    int i = blockIdx.x * 256 + threadIdx.x;
    const float* src; __half* dst; int base;
    if (i < 524288) { src = x; dst = g_xh; base = i; }
    else {
        int j = i - 524288;
        int w = j >> 17;  base = j & 131071;
        src = (w == 0) ? wq : (w == 1) ? wk : (w == 2) ? wv : wo;
        dst = g_wh[w];
    }
    float4 a = ((const float4*)src)[2*base];
    float4 b = ((const float4*)src)[2*base + 1];
    ((uint4*)dst)[base] = pack8(a, b);
}

// ---------------------------------------------------------------------------
// fp16 mma.sync GEMM (R14, frozen): block 128x128, 8 warps, warp tile
// 32(M)x64(N), K-step 32, 4 stage buffers, two slabs per barrier.
// MODE 1: QKV in ONE launch (z: 0=Wq->rope->g_qh, 1=Wk->rope->g_kh, 2=Wv).
// MODE 0: Wo GEMM, f32 outF row-major.
// ---------------------------------------------------------------------------
#define GSTR 40
#define GBUFO (128*GSTR*2)
#define GT_SMEM (8*GBUFO)               // 81920 B

template<int MODE>
__global__ __launch_bounds__(256) void gemm_k(
    float* __restrict__ outF,
    const float* __restrict__ rc, const float* __restrict__ rs)
{
    extern __shared__ __align__(16) __half gsm[];
    __half* As = gsm;
    __half* Bs = gsm + 4*128*GSTR;

    const __half* A = (MODE == 0) ? g_aoh : g_xh;
    const __half* B = (MODE == 0) ? g_wh[3] : g_wh[blockIdx.z];

    const int m0 = blockIdx.y * 128, n0 = blockIdx.x * 128;
    const int t = threadIdx.x, lane = t & 31, wid = t >> 5;
    const int wm = (wid & 3) * 32, wn = (wid >> 2) * 64;

    const int grow = t >> 1;
    const int gcol = (t & 1) * 16;
    const __half* Ag = A + (size_t)(m0 + grow) * HDIM + gcol;
    const __half* Bg = B + (size_t)(n0 + grow) * HDIM + gcol;
    const unsigned aSt = sptr(&As[grow * GSTR + gcol]);
    const unsigned bSt = sptr(&Bs[grow * GSTR + gcol]);

    const int s = lane >> 3, r = lane & 7;
    const unsigned aAddr = sptr(&As[(wm + (s & 1) * 8 + r) * GSTR + (s >> 1) * 8]);
    const unsigned bAddr = sptr(&Bs[(wn + (s & 1) * 8 + r) * GSTR + (s >> 1) * 8]);

    float c[2][8][4];
    #pragma unroll
    for (int i = 0; i < 2; i++)
        #pragma unroll
        for (int j = 0; j < 8; j++)
            #pragma unroll
            for (int q = 0; q < 4; q++) c[i][j][q] = 0.f;

    #define G_LOAD(sl, buf) do { \
        const __half* _as = Ag + (sl) * 32; \
        const __half* _bs = Bg + (sl) * 32; \
        unsigned _o = (buf) * GBUFO; \
        cpa16(aSt + _o,      _as);    cpa16(aSt + _o + 16, _as + 8); \
        cpa16(bSt + _o,      _bs);    cpa16(bSt + _o + 16, _bs + 8); \
        cp_commit(); \
    } while (0)

    G_LOAD(0, 0);
    G_LOAD(1, 1);

    const int NSL = HDIM / 32;
    for (int it = 0; it < NSL; it += 2) {
        cp_wait<0>();
        __syncthreads();
        if (it + 2 < NSL) {
            G_LOAD(it + 2, (it + 2) & 3);
            G_LOAD(it + 3, (it + 3) & 3);
        }

        #pragma unroll
        for (int h2 = 0; h2 < 2; h2++) {
            const unsigned bo = ((it + h2) & 3) * GBUFO;
            #pragma unroll
            for (int kc = 0; kc < 2; kc++) {
                unsigned aa[2][4], bb[4][4];
                #pragma unroll
                for (int mt = 0; mt < 2; mt++)
                    ldsm4(aa[mt], aAddr + bo + mt * (16 * GSTR * 2) + kc * 32);
                #pragma unroll
                for (int p = 0; p < 4; p++)
                    ldsm4(bb[p], bAddr + bo + p * (16 * GSTR * 2) + kc * 32);
                #pragma unroll
                for (int mt = 0; mt < 2; mt++)
                    #pragma unroll
                    for (int nt = 0; nt < 8; nt++)
                        mma16(c[mt][nt], aa[mt],
                              bb[nt >> 1][(nt & 1) ? 1 : 0],
                              bb[nt >> 1][(nt & 1) ? 3 : 2]);
            }
        }
    }

    const int grp = lane >> 2, tig = lane & 3;
    if (MODE == 0) {
        #pragma unroll
        for (int mt = 0; mt < 2; mt++)
            #pragma unroll
            for (int nt = 0; nt < 8; nt++) {
                int m = m0 + wm + mt * 16 + grp;
                int n = n0 + wn + nt * 8 + tig * 2;
                *(float2*)(outF + (size_t)m * HDIM + n)       = make_float2(c[mt][nt][0], c[mt][nt][1]);
                *(float2*)(outF + (size_t)(m + 8) * HDIM + n) = make_float2(c[mt][nt][2], c[mt][nt][3]);
            }
    } else if (blockIdx.z == 2) {
        const int h = (n0 + wn) >> 6;
        #pragma unroll
        for (int mt = 0; mt < 2; mt++)
            #pragma unroll
            for (int nt = 0; nt < 8; nt++) {
                int m = m0 + wm + mt * 16 + grp;
                int d = nt * 8 + tig * 2;
                int b = m >> 11, sq = m & (SEQ - 1);
                size_t off = (((size_t)(b * NHEADS + h) * SEQ) + sq) * HEADD + d;
                *(unsigned*)(g_vh + off)             = pack2(c[mt][nt][0], c[mt][nt][1]);
                *(unsigned*)(g_vh + off + 8 * HEADD) = pack2(c[mt][nt][2], c[mt][nt][3]);
            }
    } else {
        __half* dst = blockIdx.z ? g_kh : g_qh;
        const int h = (n0 + wn) >> 6;
        #pragma unroll
        for (int mt = 0; mt < 2; mt++) {
            #pragma unroll
            for (int half = 0; half < 2; half++) {
                int m  = m0 + wm + mt * 16 + grp + half * 8;
                int b  = m >> 11, sq = m & (SEQ - 1);
                size_t base = (((size_t)(b * NHEADS + h) * SEQ) + sq) * HEADD;
                const float* rcp = rc + sq * 32;
                const float* rsp = rs + sq * 32;
                const int q0 = half * 2;
                #pragma unroll
                for (int nt = 0; nt < 4; nt++) {
                    int d0 = nt * 8 + tig * 2;
                    float cc0 = rcp[d0],     ss0 = rsp[d0];
                    float cc1 = rcp[d0 + 1], ss1 = rsp[d0 + 1];
                    float x1a = c[mt][nt][q0],     x2a = c[mt][nt + 4][q0];
                    float x1b = c[mt][nt][q0 + 1], x2b = c[mt][nt + 4][q0 + 1];
                    *(unsigned*)(dst + base + d0) =
                        pack2(x1a * cc0 - x2a * ss0, x1b * cc1 - x2b * ss1);
                    *(unsigned*)(dst + base + d0 + 32) =
                        pack2(x2a * cc0 + x1a * ss0, x2b * cc1 + x1b * ss1);
                }
            }
        }
    }
}

// ---------------------------------------------------------------------------
// Flash attention v6: instruction-diet edition.
//  * S-init via mma with broadcast-zero C operand (removes 32 MOVs/tile)
//  * m tracked in log2 units, quantized to ceil -> power-of-2 alpha that
//    cancels exactly in normalization; warp-uniform ballot skips the whole
//    rescale block (~34 instr) on tiles where no row's max crosses an integer
//  * persistent Q frags, deferred l reduction, 3-deep cp.async KV pipeline
// ---------------------------------------------------------------------------
#define ASTR 72
#define KVH  (64*ASTR)
#define BUFB (KVH*2)
#define ATT_SMEM ((128*ASTR + 6*KVH) * 2)   // 73728 B

__global__ __launch_bounds__(256, 2) void attn_tc()
{
    extern __shared__ __align__(16) __half smh[];
    __half* Qs  = smh;
    __half* Ks0 = smh + 128*ASTR;
    __half* Vs0 = Ks0 + 3*KVH;

    const int bh = blockIdx.y, qt = blockIdx.x;
    const int t = threadIdx.x, lane = t & 31, wid = t >> 5;
    const int s = lane >> 3, r = lane & 7;
    const int grp = lane >> 2, tig = lane & 3;

    const __half* qp    = g_qh + ((size_t)bh * SEQ + qt * 128) * HEADD;
    const __half* kbase = g_kh + (size_t)bh * SEQ * HEADD;
    const __half* vbase = g_vh + (size_t)bh * SEQ * HEADD;

    // ---- prologue: G0 = Q ; G1 = K0/V0 ; G2 = K1/V1
    {
        const unsigned qDst = sptr(Qs) + ((t >> 1) * ASTR + (t & 1) * 32) * 2;
        const __half* qsrc = qp + (t >> 1) * HEADD + (t & 1) * 32;
        #pragma unroll
        for (int j = 0; j < 4; j++) cpa16(qDst + j * 16, qsrc + j * 8);
    }
    cp_commit();                                       // G0
    const unsigned kDst = sptr(Ks0) + ((t >> 2) * ASTR + (t & 3) * 16) * 2;
    const unsigned vDst = sptr(Vs0) + ((t >> 2) * ASTR + (t & 3) * 16) * 2;
    const int srcoff = (t >> 2) * HEADD + (t & 3) * 16;
    cpa16(kDst,      kbase + srcoff);     cpa16(kDst + 16, kbase + srcoff + 8);
    cpa16(vDst,      vbase + srcoff);     cpa16(vDst + 16, vbase + srcoff + 8);
    cp_commit();                                       // G1
    {
        const size_t t1 = (size_t)64 * HEADD;
        cpa16(kDst + BUFB,      kbase + t1 + srcoff);
        cpa16(kDst + BUFB + 16, kbase + t1 + srcoff + 8);
        cpa16(vDst + BUFB,      vbase + t1 + srcoff);
        cpa16(vDst + BUFB + 16, vbase + t1 + srcoff + 8);
        cp_commit();                                   // G2
    }

    const unsigned qA = sptr(Qs)  + ((wid * 16 + (s & 1) * 8 + r) * ASTR + (s >> 1) * 8) * 2;
    const unsigned kA = sptr(Ks0) + (((s & 1) * 8 + r) * ASTR + (s >> 1) * 8) * 2;
    const unsigned vA = sptr(Vs0) + (((s & 1) * 8 + r) * ASTR + (s >> 1) * 8) * 2;

    // ---- Q fragments: load ONCE into registers
    cp_wait<2>();
    __syncthreads();
    unsigned qf[4][4];
    #pragma unroll
    for (int kc = 0; kc < 4; kc++) ldsm4(qf[kc], qA + kc * 32);

    const float SC = 0.125f * 1.4426950408889634f;   // scale * log2(e)

    float o[8][4];
    #pragma unroll
    for (int nt = 0; nt < 8; nt++)
        { o[nt][0] = o[nt][1] = o[nt][2] = o[nt][3] = 0.f; }
    // m_u/m_d: running max in LOG2 units, quantized to integers (ceil)
    float m_u = -1e30f, m_d = -1e30f, l_u = 0.f, l_d = 0.f;

    const int NT = SEQ / 64;
    for (int kt = 0; kt < NT; kt++) {
        const int buf = kt % 3;
        cp_wait<1>();
        __syncthreads();

        // issue tile kt+2 into buffer (kt+2)%3 (clamped; never a live buffer)
        {
            const int kn = (kt + 2 < NT) ? kt + 2 : NT - 1;
            const size_t toff = (size_t)kn * 64 * HEADD;
            const unsigned nb = ((kt + 2) % 3) * BUFB;
            cpa16(kDst + nb,      kbase + toff + srcoff);
            cpa16(kDst + nb + 16, kbase + toff + srcoff + 8);
            cpa16(vDst + nb,      vbase + toff + srcoff);
            cpa16(vDst + nb + 16, vbase + toff + srcoff + 8);
            cp_commit();
        }

        // ---- S = Q K^T (warp: 16 x 64); kc=0 writes fresh via zero-C mma
        float sc[8][4];
        #pragma unroll
        for (int kc = 0; kc < 4; kc++) {
            unsigned kb[4][4];
            #pragma unroll
            for (int p = 0; p < 4; p++)
                ldsm4(kb[p], kA + buf * BUFB + p * (16 * ASTR * 2) + kc * 32);
            #pragma unroll
            for (int nt = 0; nt < 8; nt++) {
                if (kc == 0)
                    mma16_z(sc[nt], qf[0],
                            kb[nt >> 1][(nt & 1) ? 1 : 0],
                            kb[nt >> 1][(nt & 1) ? 3 : 2]);
                else
                    mma16(sc[nt], qf[kc],
                          kb[nt >> 1][(nt & 1) ? 1 : 0],
                          kb[nt >> 1][(nt & 1) ? 3 : 2]);
            }
        }

        // ---- online softmax with quantized log2-max + warp-uniform skip
        float mu = -1e30f, md = -1e30f;
        #pragma unroll
        for (int nt = 0; nt < 8; nt++) {
            mu = fmaxf(mu, fmaxf(sc[nt][0], sc[nt][1]));
            md = fmaxf(md, fmaxf(sc[nt][2], sc[nt][3]));
        }
        mu = fmaxf(mu, __shfl_xor_sync(0xffffffffu, mu, 1));
        mu = fmaxf(mu, __shfl_xor_sync(0xffffffffu, mu, 2));
        md = fmaxf(md, __shfl_xor_sync(0xffffffffu, md, 1));
        md = fmaxf(md, __shfl_xor_sync(0xffffffffu, md, 2));
        float msu = fmaxf(m_u, ceilf(mu * SC));
        float msd = fmaxf(m_d, ceilf(md * SC));
        if (__ballot_sync(0xffffffffu, (msu > m_u) || (msd > m_d))) {
            float au = ex2f(m_u - msu), ad = ex2f(m_d - msd);
            m_u = msu; m_d = msd;
            l_u *= au; l_d *= ad;
            #pragma unroll
            for (int nt = 0; nt < 8; nt++) {
                o[nt][0] *= au; o[nt][1] *= au;
                o[nt][2] *= ad; o[nt][3] *= ad;
            }
        }
        const float bu = -m_u, bd = -m_d;

        float su = 0.f, sd = 0.f;
        #pragma unroll
        for (int nt = 0; nt < 8; nt++) {
            sc[nt][0] = ex2f(fmaf(sc[nt][0], SC, bu));
            sc[nt][1] = ex2f(fmaf(sc[nt][1], SC, bu));
            sc[nt][2] = ex2f(fmaf(sc[nt][2], SC, bd));
            sc[nt][3] = ex2f(fmaf(sc[nt][3], SC, bd));
            su += sc[nt][0] + sc[nt][1];
            sd += sc[nt][2] + sc[nt][3];
        }
        l_u += su;                       // per-lane partial (reduced after loop)
        l_d += sd;

        // ---- O += P V : A-frags = repacked S; B-frags via ldmatrix.trans
        #pragma unroll
        for (int kc = 0; kc < 4; kc++) {
            unsigned af[4];
            af[0] = pack2(sc[2*kc][0],   sc[2*kc][1]);
            af[1] = pack2(sc[2*kc][2],   sc[2*kc][3]);
            af[2] = pack2(sc[2*kc+1][0], sc[2*kc+1][1]);
            af[3] = pack2(sc[2*kc+1][2], sc[2*kc+1][3]);
            #pragma unroll
            for (int p = 0; p < 4; p++) {
                unsigned vb[4];
                ldsm4t(vb, vA + buf * BUFB + kc * (16 * ASTR * 2) + p * 32);
                mma16(o[2*p],   af, vb[0], vb[1]);
                mma16(o[2*p+1], af, vb[2], vb[3]);
            }
        }
    }
    cp_wait<0>();

    // ---- final l reduction across the 4 lanes of each row group
    l_u += __shfl_xor_sync(0xffffffffu, l_u, 1);
    l_u += __shfl_xor_sync(0xffffffffu, l_u, 2);
    l_d += __shfl_xor_sync(0xffffffffu, l_d, 1);
    l_d += __shfl_xor_sync(0xffffffffu, l_d, 2);

    // ---- epilogue: normalize, write fp16 g_aoh [B,S,H]
    const int b = bh >> 4, h = bh & 15;
    const float iu = 1.f / l_u, id = 1.f / l_d;
    const int srow = qt * 128 + wid * 16 + grp;
    __half* obase = g_aoh + ((size_t)(b * SEQ + srow)) * HDIM + h * HEADD;
    #pragma unroll
    for (int nt = 0; nt < 8; nt++) {
        int d = nt * 8 + tig * 2;
        *(unsigned*)(obase + d)            = pack2(o[nt][0] * iu, o[nt][1] * iu);
        *(unsigned*)(obase + 8 * HDIM + d) = pack2(o[nt][2] * id, o[nt][3] * id);
    }
}

// ---------------------------------------------------------------------------
extern "C" void kernel_launch(void* const* d_in, const int* in_sizes, int n_in,
                              void* d_out, int out_size)
{
    const float* x  = (const float*)d_in[0];
    const float* Wq = (const float*)d_in[1];
    const float* Wk = (const float*)d_in[2];
    const float* Wv = (const float*)d_in[3];
    const float* Wo = (const float*)d_in[4];
    const float* rc = (const float*)d_in[5];
    const float* rs = (const float*)d_in[6];
    float* out = (float*)d_out;

    cudaFuncSetAttribute(attn_tc,
                         cudaFuncAttributeMaxDynamicSharedMemorySize, ATT_SMEM);
    cudaFuncSetAttribute(gemm_k<0>,
                         cudaFuncAttributeMaxDynamicSharedMemorySize, GT_SMEM);
    cudaFuncSetAttribute(gemm_k<1>,
                         cudaFuncAttributeMaxDynamicSharedMemorySize, GT_SMEM);

    cvt_all<<<4096, 256>>>(x, Wq, Wk, Wv, Wo);

    dim3 gQKV(HDIM / 128, (BATCH * SEQ) / 128, 3);  // 768 CTAs
    dim3 g1  (HDIM / 128, (BATCH * SEQ) / 128, 1);  // 256 CTAs
    gemm_k<1><<<gQKV, 256, GT_SMEM>>>(nullptr, rc, rs);      // Q+K (+rope) + V

    attn_tc<<<dim3(SEQ / 128, BATCH * NHEADS), 256, ATT_SMEM>>>();

    gemm_k<0><<<g1,  256, GT_SMEM>>>(out, nullptr, nullptr); // Wo -> out
}